// round 13
// baseline (speedup 1.0000x reference)
#include <cuda_runtime.h>
#include <cuda_fp16.h>
#include <cstdint>

#define NP 8192
#define DD 128
#define NSLICE 16
#define JSLICE 512
#define JCH 64
#define ZCUT (-25.0f)   // arg < ZCUT  =>  K := 0  (K < 1.4e-11; negligible in squared metric)

// ---------------- device scratch ----------------
__device__ uint16_t g_Ah[(size_t)NP * DD];      // YS fp16, row-major [i][d]
__device__ uint16_t g_Bh[(size_t)NP * DD];      // X  fp16, row-major [j][d]
__device__ uint16_t g_Xh[(size_t)NP * DD];      // XS fp16, row-major [j][d]
__device__ float    g_YS[(size_t)NP * DD];
__device__ float    g_qX[NP];
__device__ float    g_qY[NP];
__device__ float    g_rsp[(size_t)NSLICE * NP];
__device__ float    g_dkp[(size_t)NSLICE * NP * DD];

// ---------------- helpers ----------------
__device__ __forceinline__ uint32_t smem_u32(const void* p) {
    uint32_t a;
    asm("{ .reg .u64 t; cvta.to.shared.u64 t, %1; cvt.u32.u64 %0, t; }" : "=r"(a) : "l"(p));
    return a;
}
__device__ __forceinline__ uint32_t swz(uint32_t x) { return x ^ ((x >> 3) & 0x70); }

#define CP_ASYNC16(dst, src) \
    asm volatile("cp.async.cg.shared.global [%0], [%1], 16;" :: "r"(dst), "l"(src) : "memory")
#define CP_COMMIT() asm volatile("cp.async.commit_group;" ::: "memory")
#define CP_WAIT1()  asm volatile("cp.async.wait_group 1;" ::: "memory")

__device__ __forceinline__ void ldsm_x4(uint32_t& r0, uint32_t& r1, uint32_t& r2,
                                        uint32_t& r3, uint32_t addr) {
    asm volatile("ldmatrix.sync.aligned.m8n8.x4.shared.b16 {%0,%1,%2,%3}, [%4];"
                 : "=r"(r0), "=r"(r1), "=r"(r2), "=r"(r3) : "r"(addr));
}
__device__ __forceinline__ void ldsm_x4t(uint32_t& r0, uint32_t& r1, uint32_t& r2,
                                         uint32_t& r3, uint32_t addr) {
    asm volatile("ldmatrix.sync.aligned.m8n8.x4.trans.shared.b16 {%0,%1,%2,%3}, [%4];"
                 : "=r"(r0), "=r"(r1), "=r"(r2), "=r"(r3) : "r"(addr));
}
__device__ __forceinline__ void mma16816(float* c, uint32_t a0, uint32_t a1, uint32_t a2,
                                         uint32_t a3, uint32_t b0, uint32_t b1) {
    asm volatile(
        "mma.sync.aligned.m16n8k16.row.col.f32.f16.f16.f32 "
        "{%0,%1,%2,%3}, {%4,%5,%6,%7}, {%8,%9}, {%0,%1,%2,%3};"
        : "+f"(c[0]), "+f"(c[1]), "+f"(c[2]), "+f"(c[3])
        : "r"(a0), "r"(a1), "r"(a2), "r"(a3), "r"(b0), "r"(b1));
}
__device__ __forceinline__ uint32_t pack2h(float a, float b) {
    __half2 h = __floats2half2_rn(a, b);
    return *(uint32_t*)&h;
}
__device__ __forceinline__ void stcs2(float* p, float a, float b) {
    asm volatile("st.global.cs.v2.f32 [%0], {%1, %2};" :: "l"(p), "f"(a), "f"(b) : "memory");
}

// SMEM layout: A panel (chunk-invariant, 128 rows) + double-buffered 64-row B/XH
#define SM_A     0u              // 32 KB: 2 slabs x 16KB, [128][64] fp16
#define SM_B     32768u          // 2 bufs x 16 KB: 2 slabs x 8KB, [64][64] fp16
#define SM_XH    65536u          // 2 bufs x 16 KB
#define SM_QX    98304u          // 2 bufs x 256
#define SM_QY    98816u          // 512
#define SM_TOTAL 99328

// ===========================================================================
// prep: 8 X rows + 8 Y rows per block, 128 threads, 1024 blocks.
// ===========================================================================
__global__ __launch_bounds__(128, 8)
void prep_kernel(const float* __restrict__ X, const float* __restrict__ Y,
                 const float* __restrict__ S) {
    __shared__ float rows[16][DD];
    __shared__ float parts[4][16];

    const int c = threadIdx.x;
    const int wid = c >> 5, lane = c & 31;
    const int rowBase = blockIdx.x * 8;

#pragma unroll
    for (int r = 0; r < 8; r++) {
        rows[r][c]     = X[(size_t)(rowBase + r) * DD + c];
        rows[8 + r][c] = Y[(size_t)(rowBase + r) * DD + c];
    }
    __syncthreads();

    float acc[16];
#pragma unroll
    for (int r = 0; r < 16; r++) acc[r] = 0.f;

    for (int k = 0; k < DD; k += 4) {
#pragma unroll
        for (int kk = 0; kk < 4; kk++) {
            const float s = S[(size_t)(k + kk) * DD + c];
#pragma unroll
            for (int r = 0; r < 16; r++)
                acc[r] = fmaf(rows[r][k + kk], s, acc[r]);
        }
    }

#pragma unroll
    for (int r = 0; r < 16; r++) {
        float p = rows[r][c] * acc[r];
#pragma unroll
        for (int o = 16; o > 0; o >>= 1) p += __shfl_down_sync(0xffffffffu, p, o);
        if (lane == 0) parts[wid][r] = p;
    }
    __syncthreads();
    if (c < 16) {
        float q = (parts[0][c] + parts[1][c]) + (parts[2][c] + parts[3][c]);
        if (c < 8) g_qX[rowBase + c] = q;
        else       g_qY[rowBase + c - 8] = q;
    }

#pragma unroll
    for (int r = 0; r < 8; r++) {
        const size_t o = (size_t)(rowBase + r) * DD + c;
        g_Bh[o] = __half_as_ushort(__float2half_rn(rows[r][c]));   // X
        g_Xh[o] = __half_as_ushort(__float2half_rn(acc[r]));       // XS
        g_Ah[o] = __half_as_ushort(__float2half_rn(acc[8 + r]));   // YS
        g_YS[o] = acc[8 + r];
    }
}

// ===========================================================================
// fused: GEMM1 (YS.X^T, fp16 K=128) + exp + GEMM2 (K@XS) per 64-j chunk.
// Two warp-uniform skips: (a) if the warp tile's max arg < ZCUT, skip the
// entire exp/pack path and store zeros; (b) if all K fragments are fp16-zero,
// skip GEMM2 (bit-identical: skipped mmas were pure zero-adds).
// ===========================================================================
__global__ __launch_bounds__(256, 2)
void fused_kernel(float* __restrict__ Kout) {
    extern __shared__ char sm[];
    const uint32_t sb = smem_u32(sm);
    float* qy_s = (float*)(sm + SM_QY);

    const int tid  = threadIdx.x;
    const int w    = tid >> 5, lane = tid & 31;
    const int r    = lane >> 2, cp2 = lane & 3;
    const int iBase  = blockIdx.x * 128;
    const int slice  = blockIdx.y;
    const int jBase0 = slice * JSLICE;

    if (tid < 128) qy_s[tid] = 0.5f * g_qY[iBase + tid];

    const int row0 = iBase + w * 16 + r;
    const int lrow = (lane & 15);
    const int lcg  = (lane >> 4) * 16;

    auto load_panelA = [&]() {
        const uint16_t* src0 = g_Ah + (size_t)iBase * DD;
#pragma unroll
        for (int k = 0; k < 8; k++) {
            int u = tid + k * 256;
            int row = u >> 4, seg = u & 15;
            uint32_t dst = sb + SM_A + (uint32_t)(seg >> 3) * 16384u +
                           swz((uint32_t)(row * 128 + (seg & 7) * 16));
            CP_ASYNC16(dst, src0 + (size_t)row * DD + seg * 8);
        }
    };
    auto load_panel64 = [&](uint32_t dstBase, const uint16_t* src0) {
#pragma unroll
        for (int k = 0; k < 4; k++) {
            int u = tid + k * 256;
            int row = u >> 4, seg = u & 15;
            uint32_t dst = dstBase + (uint32_t)(seg >> 3) * 8192u +
                           swz((uint32_t)(row * 128 + (seg & 7) * 16));
            CP_ASYNC16(dst, src0 + (size_t)row * DD + seg * 8);
        }
    };
    auto load_chunk = [&](int ch) {
        const int jBase = jBase0 + ch * JCH;
        const uint32_t buf = (uint32_t)(ch & 1);
        load_panel64(sb + SM_B + buf * 16384u, g_Bh + (size_t)jBase * DD);
        load_panel64(sb + SM_XH + buf * 16384u, g_Xh + (size_t)jBase * DD);
        if (tid < 16) CP_ASYNC16(sb + SM_QX + buf * 256u + tid * 16, g_qX + jBase + tid * 4);
    };

    float dP[16][4];
#pragma unroll
    for (int t = 0; t < 16; t++)
#pragma unroll
        for (int v = 0; v < 4; v++) dP[t][v] = 0.f;
    float rs0 = 0.f, rs1 = 0.f;

    load_panelA();
    load_chunk(0);
    CP_COMMIT();

    for (int ch = 0; ch < JSLICE / JCH; ch++) {
        const int jBase = jBase0 + ch * JCH;
        const uint32_t buf = (uint32_t)(ch & 1);
        __syncthreads();
        if (ch + 1 < JSLICE / JCH) load_chunk(ch + 1);
        CP_COMMIT();
        CP_WAIT1();
        __syncthreads();

        const float* qx_s = (const float*)(sm + SM_QX + buf * 256u);

        // ---- GEMM1: c[128 x 64] = YS . X^T (K=128) ----
        float c[8][4];
#pragma unroll
        for (int t = 0; t < 8; t++)
#pragma unroll
            for (int v = 0; v < 4; v++) c[t][v] = 0.f;

#pragma unroll
        for (int half = 0; half < 2; half++) {
            const uint32_t aB = sb + SM_A + (uint32_t)half * 16384u;
            const uint32_t bB = sb + SM_B + buf * 16384u + (uint32_t)half * 8192u;
#pragma unroll
            for (int kk = 0; kk < 4; kk++) {
                uint32_t a0, a1, a2, a3;
                ldsm_x4(a0, a1, a2, a3,
                        aB + swz((uint32_t)((w * 16 + lrow) * 128 + kk * 32 + lcg)));
#pragma unroll
                for (int g = 0; g < 4; g++) {
                    uint32_t b0, b1, b2, b3;
                    ldsm_x4(b0, b1, b2, b3,
                            bB + swz((uint32_t)((g * 16 + lrow) * 128 + kk * 32 + lcg)));
                    mma16816(c[2 * g],     a0, a1, a2, a3, b0, b2);
                    mma16816(c[2 * g + 1], a0, a1, a2, a3, b1, b3);
                }
            }
        }

        // ---- epilogue: args in place, warp-uniform exp skip ----
        const float qy0 = qy_s[w * 16 + r], qy1 = qy_s[w * 16 + r + 8];
        float maxa = -1e30f;
#pragma unroll
        for (int t = 0; t < 8; t++) {
            const int jl = t * 8 + cp2 * 2;
            const float qx0 = 0.5f * qx_s[jl], qx1 = 0.5f * qx_s[jl + 1];
            c[t][0] -= qy0 + qx0;
            c[t][1] -= qy0 + qx1;
            c[t][2] -= qy1 + qx0;
            c[t][3] -= qy1 + qx1;
            maxa = fmaxf(maxa, fmaxf(fmaxf(c[t][0], c[t][1]), fmaxf(c[t][2], c[t][3])));
        }

        uint32_t khp[8][2];
        uint32_t anynz = 0;
        if (__any_sync(0xffffffffu, maxa > ZCUT)) {
#pragma unroll
            for (int t = 0; t < 8; t++) {
                const int jl = t * 8 + cp2 * 2;
                float k00 = __expf(c[t][0]);
                float k01 = __expf(c[t][1]);
                float k10 = __expf(c[t][2]);
                float k11 = __expf(c[t][3]);
                rs0 += k00 + k01;
                rs1 += k10 + k11;
                stcs2(&Kout[(size_t)row0 * NP + jBase + jl], k00, k01);
                stcs2(&Kout[(size_t)(row0 + 8) * NP + jBase + jl], k10, k11);
                khp[t][0] = pack2h(k00, k01);
                khp[t][1] = pack2h(k10, k11);
                anynz |= khp[t][0] | khp[t][1];
            }
        } else {
            // all K < 1.4e-11: store zeros, no exp, no GEMM2 contribution
#pragma unroll
            for (int t = 0; t < 8; t++) {
                const int jl = t * 8 + cp2 * 2;
                stcs2(&Kout[(size_t)row0 * NP + jBase + jl], 0.f, 0.f);
                stcs2(&Kout[(size_t)(row0 + 8) * NP + jBase + jl], 0.f, 0.f);
            }
        }

        // ---- GEMM2: dP += K @ XS — skipped when all K fragments are zero ----
        if (__any_sync(0xffffffffu, anynz != 0u)) {
#pragma unroll
            for (int kt = 0; kt < 4; kt++) {
                const uint32_t ah0 = khp[2 * kt][0], ah1 = khp[2 * kt][1];
                const uint32_t ah2 = khp[2 * kt + 1][0], ah3 = khp[2 * kt + 1][1];
#pragma unroll
                for (int half2 = 0; half2 < 2; half2++) {
                    const uint32_t xB = sb + SM_XH + buf * 16384u + (uint32_t)half2 * 8192u;
#pragma unroll
                    for (int dg = 0; dg < 4; dg++) {
                        uint32_t bh0, bh1, bh2, bh3;
                        ldsm_x4t(bh0, bh1, bh2, bh3,
                                 xB + swz((uint32_t)((kt * 16 + lrow) * 128 + dg * 32 + lcg)));
                        const int t = half2 * 8 + dg * 2;
                        mma16816(dP[t],     ah0, ah1, ah2, ah3, bh0, bh1);
                        mma16816(dP[t + 1], ah0, ah1, ah2, ah3, bh2, bh3);
                    }
                }
            }
        }
    }

    // ---- write dP partials + rowsum partials ----
#pragma unroll
    for (int t = 0; t < 16; t++) {
        const int d = t * 8 + cp2 * 2;
        float* o0 = g_dkp + (size_t)slice * NP * DD + (size_t)row0 * DD + d;
        float* o1 = g_dkp + (size_t)slice * NP * DD + (size_t)(row0 + 8) * DD + d;
        stcs2(o0, dP[t][0], dP[t][1]);
        stcs2(o1, dP[t][2], dP[t][3]);
    }
    rs0 += __shfl_xor_sync(0xffffffffu, rs0, 1);
    rs0 += __shfl_xor_sync(0xffffffffu, rs0, 2);
    rs1 += __shfl_xor_sync(0xffffffffu, rs1, 1);
    rs1 += __shfl_xor_sync(0xffffffffu, rs1, 2);
    if (cp2 == 0) {
        g_rsp[(size_t)slice * NP + row0]     = rs0;
        g_rsp[(size_t)slice * NP + row0 + 8] = rs1;
    }
}

// ===========================================================================
__global__ void dk_final_kernel(float* __restrict__ dK) {
    const size_t idx = (size_t)blockIdx.x * 256 + threadIdx.x;
    const size_t i = idx >> 7;
    float s = 0.f, p = 0.f;
#pragma unroll
    for (int h = 0; h < NSLICE; h++) {
        s += g_rsp[(size_t)h * NP + i];
        p += g_dkp[(size_t)h * NP * DD + idx];
    }
    dK[idx] = 2.0f * (s * g_YS[idx] - p);
}

// ===========================================================================
extern "C" void kernel_launch(void* const* d_in, const int* in_sizes, int n_in,
                              void* d_out, int out_size) {
    (void)in_sizes; (void)n_in; (void)out_size;
    const float* X = (const float*)d_in[0];
    const float* Y = (const float*)d_in[1];
    const float* S = (const float*)d_in[2];
    float* out   = (float*)d_out;
    float* Kout  = out;
    float* dKout = out + (size_t)NP * NP;

    cudaFuncSetAttribute(fused_kernel, cudaFuncAttributeMaxDynamicSharedMemorySize, SM_TOTAL);

    prep_kernel<<<NP / 8, 128>>>(X, Y, S);

    dim3 gf(NP / 128, NSLICE);
    fused_kernel<<<gf, 256, SM_TOTAL>>>(Kout);

    dk_final_kernel<<<(NP * DD) / 256, 256>>>(dKout);
}

// round 14
// speedup vs baseline: 1.2652x; 1.2652x over previous
#include <cuda_runtime.h>
#include <cuda_fp16.h>
#include <cstdint>

#define NP 8192
#define DD 128
#define NSLICE 16
#define JSLICE 512
#define JCH 64

// ---------------- device scratch ----------------
__device__ uint16_t g_Ah[(size_t)NP * DD];      // YS fp16, row-major [i][d]
__device__ uint16_t g_Bh[(size_t)NP * DD];      // X  fp16, row-major [j][d]
__device__ uint16_t g_Xh[(size_t)NP * DD];      // XS fp16, row-major [j][d]
__device__ float    g_YS[(size_t)NP * DD];
__device__ float    g_qX[NP];
__device__ float    g_qY[NP];
__device__ float    g_rsp[(size_t)NSLICE * NP];
__device__ uint32_t g_dkph[(size_t)NSLICE * NP * (DD / 2)];  // dP partials, packed half2

// ---------------- helpers ----------------
__device__ __forceinline__ uint32_t smem_u32(const void* p) {
    uint32_t a;
    asm("{ .reg .u64 t; cvta.to.shared.u64 t, %1; cvt.u32.u64 %0, t; }" : "=r"(a) : "l"(p));
    return a;
}
__device__ __forceinline__ uint32_t swz(uint32_t x) { return x ^ ((x >> 3) & 0x70); }

#define CP_ASYNC16(dst, src) \
    asm volatile("cp.async.cg.shared.global [%0], [%1], 16;" :: "r"(dst), "l"(src) : "memory")
#define CP_COMMIT() asm volatile("cp.async.commit_group;" ::: "memory")
#define CP_WAIT1()  asm volatile("cp.async.wait_group 1;" ::: "memory")

__device__ __forceinline__ void ldsm_x4(uint32_t& r0, uint32_t& r1, uint32_t& r2,
                                        uint32_t& r3, uint32_t addr) {
    asm volatile("ldmatrix.sync.aligned.m8n8.x4.shared.b16 {%0,%1,%2,%3}, [%4];"
                 : "=r"(r0), "=r"(r1), "=r"(r2), "=r"(r3) : "r"(addr));
}
__device__ __forceinline__ void ldsm_x4t(uint32_t& r0, uint32_t& r1, uint32_t& r2,
                                         uint32_t& r3, uint32_t addr) {
    asm volatile("ldmatrix.sync.aligned.m8n8.x4.trans.shared.b16 {%0,%1,%2,%3}, [%4];"
                 : "=r"(r0), "=r"(r1), "=r"(r2), "=r"(r3) : "r"(addr));
}
__device__ __forceinline__ void mma16816(float* c, uint32_t a0, uint32_t a1, uint32_t a2,
                                         uint32_t a3, uint32_t b0, uint32_t b1) {
    asm volatile(
        "mma.sync.aligned.m16n8k16.row.col.f32.f16.f16.f32 "
        "{%0,%1,%2,%3}, {%4,%5,%6,%7}, {%8,%9}, {%0,%1,%2,%3};"
        : "+f"(c[0]), "+f"(c[1]), "+f"(c[2]), "+f"(c[3])
        : "r"(a0), "r"(a1), "r"(a2), "r"(a3), "r"(b0), "r"(b1));
}
__device__ __forceinline__ uint32_t pack2h(float a, float b) {
    __half2 h = __floats2half2_rn(a, b);
    return *(uint32_t*)&h;
}
__device__ __forceinline__ void stcs2(float* p, float a, float b) {
    asm volatile("st.global.cs.v2.f32 [%0], {%1, %2};" :: "l"(p), "f"(a), "f"(b) : "memory");
}
__device__ __forceinline__ void stcs1u(uint32_t* p, uint32_t v) {
    asm volatile("st.global.cs.u32 [%0], %1;" :: "l"(p), "r"(v) : "memory");
}

// SMEM layout: A panel (chunk-invariant, 128 rows) + double-buffered 64-row B/XH
#define SM_A     0u              // 32 KB: 2 slabs x 16KB, [128][64] fp16
#define SM_B     32768u          // 2 bufs x 16 KB: 2 slabs x 8KB, [64][64] fp16
#define SM_XH    65536u          // 2 bufs x 16 KB
#define SM_QX    98304u          // 2 bufs x 256
#define SM_QY    98816u          // 512
#define SM_TOTAL 99328

// ===========================================================================
// prep: 8 X rows + 8 Y rows per block, 128 threads, 1024 blocks.
// ===========================================================================
__global__ __launch_bounds__(128, 8)
void prep_kernel(const float* __restrict__ X, const float* __restrict__ Y,
                 const float* __restrict__ S) {
    __shared__ float rows[16][DD];
    __shared__ float parts[4][16];

    const int c = threadIdx.x;
    const int wid = c >> 5, lane = c & 31;
    const int rowBase = blockIdx.x * 8;

#pragma unroll
    for (int r = 0; r < 8; r++) {
        rows[r][c]     = X[(size_t)(rowBase + r) * DD + c];
        rows[8 + r][c] = Y[(size_t)(rowBase + r) * DD + c];
    }
    __syncthreads();

    float acc[16];
#pragma unroll
    for (int r = 0; r < 16; r++) acc[r] = 0.f;

    for (int k = 0; k < DD; k += 4) {
#pragma unroll
        for (int kk = 0; kk < 4; kk++) {
            const float s = S[(size_t)(k + kk) * DD + c];
#pragma unroll
            for (int r = 0; r < 16; r++)
                acc[r] = fmaf(rows[r][k + kk], s, acc[r]);
        }
    }

#pragma unroll
    for (int r = 0; r < 16; r++) {
        float p = rows[r][c] * acc[r];
#pragma unroll
        for (int o = 16; o > 0; o >>= 1) p += __shfl_down_sync(0xffffffffu, p, o);
        if (lane == 0) parts[wid][r] = p;
    }
    __syncthreads();
    if (c < 16) {
        float q = (parts[0][c] + parts[1][c]) + (parts[2][c] + parts[3][c]);
        if (c < 8) g_qX[rowBase + c] = q;
        else       g_qY[rowBase + c - 8] = q;
    }

#pragma unroll
    for (int r = 0; r < 8; r++) {
        const size_t o = (size_t)(rowBase + r) * DD + c;
        g_Bh[o] = __half_as_ushort(__float2half_rn(rows[r][c]));   // X
        g_Xh[o] = __half_as_ushort(__float2half_rn(acc[r]));       // XS
        g_Ah[o] = __half_as_ushort(__float2half_rn(acc[8 + r]));   // YS
        g_YS[o] = acc[8 + r];
    }
}

// ===========================================================================
// fused (R11 structure): GEMM1 (YS.X^T, fp16 K=128) + exp + GEMM2 (K@XS)
// per 64-j chunk; GEMM2 skipped when all K fragments are fp16-zero.
// dP partials stored as packed half2 (register-neutral: converted at end).
// ===========================================================================
__global__ __launch_bounds__(256, 2)
void fused_kernel(float* __restrict__ Kout) {
    extern __shared__ char sm[];
    const uint32_t sb = smem_u32(sm);
    float* qy_s = (float*)(sm + SM_QY);

    const int tid  = threadIdx.x;
    const int w    = tid >> 5, lane = tid & 31;
    const int r    = lane >> 2, cp2 = lane & 3;
    const int iBase  = blockIdx.x * 128;
    const int slice  = blockIdx.y;
    const int jBase0 = slice * JSLICE;

    if (tid < 128) qy_s[tid] = 0.5f * g_qY[iBase + tid];

    const int row0 = iBase + w * 16 + r;
    const int lrow = (lane & 15);
    const int lcg  = (lane >> 4) * 16;

    auto load_panelA = [&]() {
        const uint16_t* src0 = g_Ah + (size_t)iBase * DD;
#pragma unroll
        for (int k = 0; k < 8; k++) {
            int u = tid + k * 256;
            int row = u >> 4, seg = u & 15;
            uint32_t dst = sb + SM_A + (uint32_t)(seg >> 3) * 16384u +
                           swz((uint32_t)(row * 128 + (seg & 7) * 16));
            CP_ASYNC16(dst, src0 + (size_t)row * DD + seg * 8);
        }
    };
    auto load_panel64 = [&](uint32_t dstBase, const uint16_t* src0) {
#pragma unroll
        for (int k = 0; k < 4; k++) {
            int u = tid + k * 256;
            int row = u >> 4, seg = u & 15;
            uint32_t dst = dstBase + (uint32_t)(seg >> 3) * 8192u +
                           swz((uint32_t)(row * 128 + (seg & 7) * 16));
            CP_ASYNC16(dst, src0 + (size_t)row * DD + seg * 8);
        }
    };
    auto load_chunk = [&](int ch) {
        const int jBase = jBase0 + ch * JCH;
        const uint32_t buf = (uint32_t)(ch & 1);
        load_panel64(sb + SM_B + buf * 16384u, g_Bh + (size_t)jBase * DD);
        load_panel64(sb + SM_XH + buf * 16384u, g_Xh + (size_t)jBase * DD);
        if (tid < 16) CP_ASYNC16(sb + SM_QX + buf * 256u + tid * 16, g_qX + jBase + tid * 4);
    };

    float dP[16][4];
#pragma unroll
    for (int t = 0; t < 16; t++)
#pragma unroll
        for (int v = 0; v < 4; v++) dP[t][v] = 0.f;
    float rs0 = 0.f, rs1 = 0.f;

    load_panelA();
    load_chunk(0);
    CP_COMMIT();

    for (int ch = 0; ch < JSLICE / JCH; ch++) {
        const int jBase = jBase0 + ch * JCH;
        const uint32_t buf = (uint32_t)(ch & 1);
        __syncthreads();
        if (ch + 1 < JSLICE / JCH) load_chunk(ch + 1);
        CP_COMMIT();
        CP_WAIT1();
        __syncthreads();

        const float* qx_s = (const float*)(sm + SM_QX + buf * 256u);

        // ---- GEMM1: c[128 x 64] = YS . X^T (K=128) ----
        float c[8][4];
#pragma unroll
        for (int t = 0; t < 8; t++)
#pragma unroll
            for (int v = 0; v < 4; v++) c[t][v] = 0.f;

#pragma unroll
        for (int half = 0; half < 2; half++) {
            const uint32_t aB = sb + SM_A + (uint32_t)half * 16384u;
            const uint32_t bB = sb + SM_B + buf * 16384u + (uint32_t)half * 8192u;
#pragma unroll
            for (int kk = 0; kk < 4; kk++) {
                uint32_t a0, a1, a2, a3;
                ldsm_x4(a0, a1, a2, a3,
                        aB + swz((uint32_t)((w * 16 + lrow) * 128 + kk * 32 + lcg)));
#pragma unroll
                for (int g = 0; g < 4; g++) {
                    uint32_t b0, b1, b2, b3;
                    ldsm_x4(b0, b1, b2, b3,
                            bB + swz((uint32_t)((g * 16 + lrow) * 128 + kk * 32 + lcg)));
                    mma16816(c[2 * g],     a0, a1, a2, a3, b0, b2);
                    mma16816(c[2 * g + 1], a0, a1, a2, a3, b1, b3);
                }
            }
        }

        // ---- epilogue: K = exp(dot - 0.5*(qY+qX)) ----
        const float qy0 = qy_s[w * 16 + r], qy1 = qy_s[w * 16 + r + 8];
        uint32_t khp[8][2];
        uint32_t anynz = 0;
#pragma unroll
        for (int t = 0; t < 8; t++) {
            const int jl = t * 8 + cp2 * 2;
            const float qx0 = 0.5f * qx_s[jl], qx1 = 0.5f * qx_s[jl + 1];
            float k00 = __expf(c[t][0] - qy0 - qx0);
            float k01 = __expf(c[t][1] - qy0 - qx1);
            float k10 = __expf(c[t][2] - qy1 - qx0);
            float k11 = __expf(c[t][3] - qy1 - qx1);
            rs0 += k00 + k01;
            rs1 += k10 + k11;
            stcs2(&Kout[(size_t)row0 * NP + jBase + jl], k00, k01);
            stcs2(&Kout[(size_t)(row0 + 8) * NP + jBase + jl], k10, k11);
            khp[t][0] = pack2h(k00, k01);
            khp[t][1] = pack2h(k10, k11);
            anynz |= khp[t][0] | khp[t][1];
        }

        // ---- GEMM2: dP += K @ XS — skipped when all K fragments are zero ----
        if (__any_sync(0xffffffffu, anynz != 0u)) {
#pragma unroll
            for (int kt = 0; kt < 4; kt++) {
                const uint32_t ah0 = khp[2 * kt][0], ah1 = khp[2 * kt][1];
                const uint32_t ah2 = khp[2 * kt + 1][0], ah3 = khp[2 * kt + 1][1];
#pragma unroll
                for (int half2 = 0; half2 < 2; half2++) {
                    const uint32_t xB = sb + SM_XH + buf * 16384u + (uint32_t)half2 * 8192u;
#pragma unroll
                    for (int dg = 0; dg < 4; dg++) {
                        uint32_t bh0, bh1, bh2, bh3;
                        ldsm_x4t(bh0, bh1, bh2, bh3,
                                 xB + swz((uint32_t)((kt * 16 + lrow) * 128 + dg * 32 + lcg)));
                        const int t = half2 * 8 + dg * 2;
                        mma16816(dP[t],     ah0, ah1, ah2, ah3, bh0, bh1);
                        mma16816(dP[t + 1], ah0, ah1, ah2, ah3, bh2, bh3);
                    }
                }
            }
        }
    }

    // ---- write dP partials (packed half2) + rowsum partials ----
#pragma unroll
    for (int t = 0; t < 16; t++) {
        const int d = t * 8 + cp2 * 2;                 // even; pair (d, d+1)
        uint32_t* o0 = g_dkph + (size_t)slice * NP * (DD / 2)
                              + (size_t)row0 * (DD / 2) + (d >> 1);
        uint32_t* o1 = g_dkph + (size_t)slice * NP * (DD / 2)
                              + (size_t)(row0 + 8) * (DD / 2) + (d >> 1);
        stcs1u(o0, pack2h(dP[t][0], dP[t][1]));
        stcs1u(o1, pack2h(dP[t][2], dP[t][3]));
    }
    rs0 += __shfl_xor_sync(0xffffffffu, rs0, 1);
    rs0 += __shfl_xor_sync(0xffffffffu, rs0, 2);
    rs1 += __shfl_xor_sync(0xffffffffu, rs1, 1);
    rs1 += __shfl_xor_sync(0xffffffffu, rs1, 2);
    if (cp2 == 0) {
        g_rsp[(size_t)slice * NP + row0]     = rs0;
        g_rsp[(size_t)slice * NP + row0 + 8] = rs1;
    }
}

// ===========================================================================
// dk_final: one thread per (i, d-pair). Reads half2 partials, fp32 accumulate.
// ===========================================================================
__global__ void dk_final_kernel(float* __restrict__ dK) {
    const size_t idx2 = (size_t)blockIdx.x * 256 + threadIdx.x;   // [0, NP*64)
    const size_t i = idx2 >> 6;
    const int dp = (int)(idx2 & 63);
    float s = 0.f, p0 = 0.f, p1 = 0.f;
#pragma unroll
    for (int h = 0; h < NSLICE; h++) {
        s += g_rsp[(size_t)h * NP + i];
        const uint32_t v = g_dkph[(size_t)h * NP * (DD / 2) + idx2];
        const __half2 h2 = *(const __half2*)&v;
        p0 += __low2float(h2);
        p1 += __high2float(h2);
    }
    const size_t ob = i * DD + (size_t)dp * 2;
    dK[ob]     = 2.0f * (s * g_YS[ob]     - p0);
    dK[ob + 1] = 2.0f * (s * g_YS[ob + 1] - p1);
}

// ===========================================================================
extern "C" void kernel_launch(void* const* d_in, const int* in_sizes, int n_in,
                              void* d_out, int out_size) {
    (void)in_sizes; (void)n_in; (void)out_size;
    const float* X = (const float*)d_in[0];
    const float* Y = (const float*)d_in[1];
    const float* S = (const float*)d_in[2];
    float* out   = (float*)d_out;
    float* Kout  = out;
    float* dKout = out + (size_t)NP * NP;

    cudaFuncSetAttribute(fused_kernel, cudaFuncAttributeMaxDynamicSharedMemorySize, SM_TOTAL);

    prep_kernel<<<NP / 8, 128>>>(X, Y, S);

    dim3 gf(NP / 128, NSLICE);
    fused_kernel<<<gf, 256, SM_TOTAL>>>(Kout);

    dk_final_kernel<<<(NP * 64) / 256, 256>>>(dKout);
}

// round 15
// speedup vs baseline: 1.2980x; 1.0259x over previous
#include <cuda_runtime.h>
#include <cuda_fp16.h>
#include <cstdint>

#define NP 8192
#define DD 128
#define NSLICE 16
#define JSLICE 512
#define JCH 64
#define L2E  1.44269504f
#define HL2E 0.72134752f

// ---------------- device scratch ----------------
__device__ uint16_t g_Ah[(size_t)NP * DD];      // L2E * YS fp16, row-major [i][d]
__device__ uint16_t g_Bh[(size_t)NP * DD];      // X  fp16, row-major [j][d]
__device__ uint16_t g_Xh[(size_t)NP * DD];      // XS fp16, row-major [j][d]
__device__ float    g_YS[(size_t)NP * DD];
__device__ float    g_qXl[NP];                  // 0.5*L2E*qX
__device__ float    g_qY[NP];
__device__ float    g_rsp[(size_t)NSLICE * NP];
__device__ uint32_t g_dkph[(size_t)NSLICE * NP * (DD / 2)];  // dP partials, packed half2

// ---------------- helpers ----------------
__device__ __forceinline__ uint32_t smem_u32(const void* p) {
    uint32_t a;
    asm("{ .reg .u64 t; cvta.to.shared.u64 t, %1; cvt.u32.u64 %0, t; }" : "=r"(a) : "l"(p));
    return a;
}
__device__ __forceinline__ uint32_t swz(uint32_t x) { return x ^ ((x >> 3) & 0x70); }
__device__ __forceinline__ float ex2f(float x) {
    float y;
    asm("ex2.approx.f32 %0, %1;" : "=f"(y) : "f"(x));
    return y;
}

#define CP_ASYNC16(dst, src) \
    asm volatile("cp.async.cg.shared.global [%0], [%1], 16;" :: "r"(dst), "l"(src) : "memory")
#define CP_COMMIT() asm volatile("cp.async.commit_group;" ::: "memory")
#define CP_WAIT1()  asm volatile("cp.async.wait_group 1;" ::: "memory")

__device__ __forceinline__ void ldsm_x4(uint32_t& r0, uint32_t& r1, uint32_t& r2,
                                        uint32_t& r3, uint32_t addr) {
    asm volatile("ldmatrix.sync.aligned.m8n8.x4.shared.b16 {%0,%1,%2,%3}, [%4];"
                 : "=r"(r0), "=r"(r1), "=r"(r2), "=r"(r3) : "r"(addr));
}
__device__ __forceinline__ void ldsm_x4t(uint32_t& r0, uint32_t& r1, uint32_t& r2,
                                         uint32_t& r3, uint32_t addr) {
    asm volatile("ldmatrix.sync.aligned.m8n8.x4.trans.shared.b16 {%0,%1,%2,%3}, [%4];"
                 : "=r"(r0), "=r"(r1), "=r"(r2), "=r"(r3) : "r"(addr));
}
__device__ __forceinline__ void mma16816(float* c, uint32_t a0, uint32_t a1, uint32_t a2,
                                         uint32_t a3, uint32_t b0, uint32_t b1) {
    asm volatile(
        "mma.sync.aligned.m16n8k16.row.col.f32.f16.f16.f32 "
        "{%0,%1,%2,%3}, {%4,%5,%6,%7}, {%8,%9}, {%0,%1,%2,%3};"
        : "+f"(c[0]), "+f"(c[1]), "+f"(c[2]), "+f"(c[3])
        : "r"(a0), "r"(a1), "r"(a2), "r"(a3), "r"(b0), "r"(b1));
}
__device__ __forceinline__ uint32_t pack2h(float a, float b) {
    __half2 h = __floats2half2_rn(a, b);
    return *(uint32_t*)&h;
}
__device__ __forceinline__ void stcs2(float* p, float a, float b) {
    asm volatile("st.global.cs.v2.f32 [%0], {%1, %2};" :: "l"(p), "f"(a), "f"(b) : "memory");
}
__device__ __forceinline__ void stcs1u(uint32_t* p, uint32_t v) {
    asm volatile("st.global.cs.u32 [%0], %1;" :: "l"(p), "r"(v) : "memory");
}

// SMEM layout: A panel (chunk-invariant, 128 rows) + double-buffered 64-row B/XH
#define SM_A     0u              // 32 KB: 2 slabs x 16KB, [128][64] fp16
#define SM_B     32768u          // 2 bufs x 16 KB: 2 slabs x 8KB, [64][64] fp16
#define SM_XH    65536u          // 2 bufs x 16 KB
#define SM_QX    98304u          // 2 bufs x 256
#define SM_QY    98816u          // 512
#define SM_TOTAL 99328

// ===========================================================================
// prep: 8 X rows + 8 Y rows per block, 128 threads, 1024 blocks.
// rows reads vectorized (float4 broadcast LDS).
// ===========================================================================
__global__ __launch_bounds__(128, 8)
void prep_kernel(const float* __restrict__ X, const float* __restrict__ Y,
                 const float* __restrict__ S) {
    __shared__ float rows[16][DD];
    __shared__ float parts[4][16];

    const int c = threadIdx.x;
    const int wid = c >> 5, lane = c & 31;
    const int rowBase = blockIdx.x * 8;

#pragma unroll
    for (int r = 0; r < 8; r++) {
        rows[r][c]     = X[(size_t)(rowBase + r) * DD + c];
        rows[8 + r][c] = Y[(size_t)(rowBase + r) * DD + c];
    }
    __syncthreads();

    float acc[16];
#pragma unroll
    for (int r = 0; r < 16; r++) acc[r] = 0.f;

    for (int k = 0; k < DD; k += 4) {
        const float s0 = S[(size_t)(k + 0) * DD + c];
        const float s1 = S[(size_t)(k + 1) * DD + c];
        const float s2 = S[(size_t)(k + 2) * DD + c];
        const float s3 = S[(size_t)(k + 3) * DD + c];
#pragma unroll
        for (int r = 0; r < 16; r++) {
            const float4 rv = *(const float4*)&rows[r][k];
            acc[r] = fmaf(rv.x, s0, acc[r]);
            acc[r] = fmaf(rv.y, s1, acc[r]);
            acc[r] = fmaf(rv.z, s2, acc[r]);
            acc[r] = fmaf(rv.w, s3, acc[r]);
        }
    }

#pragma unroll
    for (int r = 0; r < 16; r++) {
        float p = rows[r][c] * acc[r];
#pragma unroll
        for (int o = 16; o > 0; o >>= 1) p += __shfl_down_sync(0xffffffffu, p, o);
        if (lane == 0) parts[wid][r] = p;
    }
    __syncthreads();
    if (c < 16) {
        float q = (parts[0][c] + parts[1][c]) + (parts[2][c] + parts[3][c]);
        if (c < 8) g_qXl[rowBase + c] = HL2E * q;
        else       g_qY[rowBase + c - 8] = q;
    }

#pragma unroll
    for (int r = 0; r < 8; r++) {
        const size_t o = (size_t)(rowBase + r) * DD + c;
        g_Bh[o] = __half_as_ushort(__float2half_rn(rows[r][c]));           // X
        g_Xh[o] = __half_as_ushort(__float2half_rn(acc[r]));               // XS
        g_Ah[o] = __half_as_ushort(__float2half_rn(acc[8 + r] * L2E));     // L2E*YS
        g_YS[o] = acc[8 + r];
    }
}

// ===========================================================================
// fused: GEMM1 ((L*YS).X^T, fp16 K=128) + exp2 + GEMM2 (K@XS) per 64-j chunk.
// GEMM2 skipped when all K fragments are fp16-zero (bit-identical).
// ===========================================================================
__global__ __launch_bounds__(256, 2)
void fused_kernel(float* __restrict__ Kout) {
    extern __shared__ char sm[];
    const uint32_t sb = smem_u32(sm);
    float* qy_s = (float*)(sm + SM_QY);

    const int tid  = threadIdx.x;
    const int w    = tid >> 5, lane = tid & 31;
    const int r    = lane >> 2, cp2 = lane & 3;
    const int iBase  = blockIdx.x * 128;
    const int slice  = blockIdx.y;
    const int jBase0 = slice * JSLICE;

    if (tid < 128) qy_s[tid] = HL2E * g_qY[iBase + tid];

    const int row0 = iBase + w * 16 + r;
    const int lrow = (lane & 15);
    const int lcg  = (lane >> 4) * 16;

    auto load_panelA = [&]() {
        const uint16_t* src0 = g_Ah + (size_t)iBase * DD;
#pragma unroll
        for (int k = 0; k < 8; k++) {
            int u = tid + k * 256;
            int row = u >> 4, seg = u & 15;
            uint32_t dst = sb + SM_A + (uint32_t)(seg >> 3) * 16384u +
                           swz((uint32_t)(row * 128 + (seg & 7) * 16));
            CP_ASYNC16(dst, src0 + (size_t)row * DD + seg * 8);
        }
    };
    auto load_panel64 = [&](uint32_t dstBase, const uint16_t* src0) {
#pragma unroll
        for (int k = 0; k < 4; k++) {
            int u = tid + k * 256;
            int row = u >> 4, seg = u & 15;
            uint32_t dst = dstBase + (uint32_t)(seg >> 3) * 8192u +
                           swz((uint32_t)(row * 128 + (seg & 7) * 16));
            CP_ASYNC16(dst, src0 + (size_t)row * DD + seg * 8);
        }
    };
    auto load_chunk = [&](int ch) {
        const int jBase = jBase0 + ch * JCH;
        const uint32_t buf = (uint32_t)(ch & 1);
        load_panel64(sb + SM_B + buf * 16384u, g_Bh + (size_t)jBase * DD);
        load_panel64(sb + SM_XH + buf * 16384u, g_Xh + (size_t)jBase * DD);
        if (tid < 16) CP_ASYNC16(sb + SM_QX + buf * 256u + tid * 16, g_qXl + jBase + tid * 4);
    };

    float dP[16][4];
#pragma unroll
    for (int t = 0; t < 16; t++)
#pragma unroll
        for (int v = 0; v < 4; v++) dP[t][v] = 0.f;
    float rs0 = 0.f, rs1 = 0.f;

    load_panelA();
    load_chunk(0);
    CP_COMMIT();

    for (int ch = 0; ch < JSLICE / JCH; ch++) {
        const int jBase = jBase0 + ch * JCH;
        const uint32_t buf = (uint32_t)(ch & 1);
        __syncthreads();
        if (ch + 1 < JSLICE / JCH) load_chunk(ch + 1);
        CP_COMMIT();
        CP_WAIT1();
        __syncthreads();

        const float* qx_s = (const float*)(sm + SM_QX + buf * 256u);

        // ---- GEMM1: c[128 x 64] = (L*YS) . X^T (K=128) ----
        float c[8][4];
#pragma unroll
        for (int t = 0; t < 8; t++)
#pragma unroll
            for (int v = 0; v < 4; v++) c[t][v] = 0.f;

#pragma unroll
        for (int half = 0; half < 2; half++) {
            const uint32_t aB = sb + SM_A + (uint32_t)half * 16384u;
            const uint32_t bB = sb + SM_B + buf * 16384u + (uint32_t)half * 8192u;
#pragma unroll
            for (int kk = 0; kk < 4; kk++) {
                uint32_t a0, a1, a2, a3;
                ldsm_x4(a0, a1, a2, a3,
                        aB + swz((uint32_t)((w * 16 + lrow) * 128 + kk * 32 + lcg)));
#pragma unroll
                for (int g = 0; g < 4; g++) {
                    uint32_t b0, b1, b2, b3;
                    ldsm_x4(b0, b1, b2, b3,
                            bB + swz((uint32_t)((g * 16 + lrow) * 128 + kk * 32 + lcg)));
                    mma16816(c[2 * g],     a0, a1, a2, a3, b0, b2);
                    mma16816(c[2 * g + 1], a0, a1, a2, a3, b1, b3);
                }
            }
        }

        // ---- epilogue: K = exp2(c - qyL - qxL) ----
        const float qy0 = qy_s[w * 16 + r], qy1 = qy_s[w * 16 + r + 8];
        uint32_t khp[8][2];
        uint32_t anynz = 0;
#pragma unroll
        for (int t = 0; t < 8; t++) {
            const int jl = t * 8 + cp2 * 2;
            const float qx0 = qx_s[jl], qx1 = qx_s[jl + 1];
            float k00 = ex2f(c[t][0] - qy0 - qx0);
            float k01 = ex2f(c[t][1] - qy0 - qx1);
            float k10 = ex2f(c[t][2] - qy1 - qx0);
            float k11 = ex2f(c[t][3] - qy1 - qx1);
            rs0 += k00 + k01;
            rs1 += k10 + k11;
            stcs2(&Kout[(size_t)row0 * NP + jBase + jl], k00, k01);
            stcs2(&Kout[(size_t)(row0 + 8) * NP + jBase + jl], k10, k11);
            khp[t][0] = pack2h(k00, k01);
            khp[t][1] = pack2h(k10, k11);
            anynz |= khp[t][0] | khp[t][1];
        }

        // ---- GEMM2: dP += K @ XS — skipped when all K fragments are zero ----
        if (__any_sync(0xffffffffu, anynz != 0u)) {
#pragma unroll
            for (int kt = 0; kt < 4; kt++) {
                const uint32_t ah0 = khp[2 * kt][0], ah1 = khp[2 * kt][1];
                const uint32_t ah2 = khp[2 * kt + 1][0], ah3 = khp[2 * kt + 1][1];
#pragma unroll
                for (int half2 = 0; half2 < 2; half2++) {
                    const uint32_t xB = sb + SM_XH + buf * 16384u + (uint32_t)half2 * 8192u;
#pragma unroll
                    for (int dg = 0; dg < 4; dg++) {
                        uint32_t bh0, bh1, bh2, bh3;
                        ldsm_x4t(bh0, bh1, bh2, bh3,
                                 xB + swz((uint32_t)((kt * 16 + lrow) * 128 + dg * 32 + lcg)));
                        const int t = half2 * 8 + dg * 2;
                        mma16816(dP[t],     ah0, ah1, ah2, ah3, bh0, bh1);
                        mma16816(dP[t + 1], ah0, ah1, ah2, ah3, bh2, bh3);
                    }
                }
            }
        }
    }

    // ---- write dP partials (packed half2) + rowsum partials ----
#pragma unroll
    for (int t = 0; t < 16; t++) {
        const int d = t * 8 + cp2 * 2;
        uint32_t* o0 = g_dkph + (size_t)slice * NP * (DD / 2)
                              + (size_t)row0 * (DD / 2) + (d >> 1);
        uint32_t* o1 = g_dkph + (size_t)slice * NP * (DD / 2)
                              + (size_t)(row0 + 8) * (DD / 2) + (d >> 1);
        stcs1u(o0, pack2h(dP[t][0], dP[t][1]));
        stcs1u(o1, pack2h(dP[t][2], dP[t][3]));
    }
    rs0 += __shfl_xor_sync(0xffffffffu, rs0, 1);
    rs0 += __shfl_xor_sync(0xffffffffu, rs0, 2);
    rs1 += __shfl_xor_sync(0xffffffffu, rs1, 1);
    rs1 += __shfl_xor_sync(0xffffffffu, rs1, 2);
    if (cp2 == 0) {
        g_rsp[(size_t)slice * NP + row0]     = rs0;
        g_rsp[(size_t)slice * NP + row0 + 8] = rs1;
    }
}

// ===========================================================================
// dk_final: one thread per (i, d-pair). Reads half2 partials, fp32 accumulate.
// ===========================================================================
__global__ void dk_final_kernel(float* __restrict__ dK) {
    const size_t idx2 = (size_t)blockIdx.x * 256 + threadIdx.x;   // [0, NP*64)
    const size_t i = idx2 >> 6;
    const int dp = (int)(idx2 & 63);
    float s = 0.f, p0 = 0.f, p1 = 0.f;
#pragma unroll
    for (int h = 0; h < NSLICE; h++) {
        s += g_rsp[(size_t)h * NP + i];
        const uint32_t v = g_dkph[(size_t)h * NP * (DD / 2) + idx2];
        const __half2 h2 = *(const __half2*)&v;
        p0 += __low2float(h2);
        p1 += __high2float(h2);
    }
    const size_t ob = i * DD + (size_t)dp * 2;
    dK[ob]     = 2.0f * (s * g_YS[ob]     - p0);
    dK[ob + 1] = 2.0f * (s * g_YS[ob + 1] - p1);
}

// ===========================================================================
extern "C" void kernel_launch(void* const* d_in, const int* in_sizes, int n_in,
                              void* d_out, int out_size) {
    (void)in_sizes; (void)n_in; (void)out_size;
    const float* X = (const float*)d_in[0];
    const float* Y = (const float*)d_in[1];
    const float* S = (const float*)d_in[2];
    float* out   = (float*)d_out;
    float* Kout  = out;
    float* dKout = out + (size_t)NP * NP;

    cudaFuncSetAttribute(fused_kernel, cudaFuncAttributeMaxDynamicSharedMemorySize, SM_TOTAL);

    prep_kernel<<<NP / 8, 128>>>(X, Y, S);

    dim3 gf(NP / 128, NSLICE);
    fused_kernel<<<gf, 256, SM_TOTAL>>>(Kout);

    dk_final_kernel<<<(NP * 64) / 256, 256>>>(dKout);
}